// round 5
// baseline (speedup 1.0000x reference)
#include <cuda_runtime.h>
#include <cuda_bf16.h>

// Haar DWT (pywt 'haar', torch-style flipped filters + cross-correlation):
//   a=x[h,w] b=x[h,w+1] c=x[h+1,w] d=x[h+1,w+1]  (zero pad right/bottom)
//   LL=.5(a+b+c+d)  LH=.5(a+b-c-d)  HL=.5(a-b+c-d)  HH=.5(a-b-c+d)
// out[b, 4c+k, h, w]  ->  plane index 4*(b*C+c)+k
//
// R5: warp owns 4 consecutive output rows with vertical register carry.
// Each iteration: load next input row (2x 512B/warp LDG.128), shuffle
// horizontal neighbors, store previous output row (8x 512B/warp STG.128).
// ~2 loads per output row (vs 4 in R3); loads issue right behind stores.

#define DWT_W 256
#define DWT_H 256
#define W4    (DWT_W / 4)
#define PLANE4 ((size_t)DWT_H * W4)
#define FULL  0xffffffffu
#define ROWS  4

__device__ __forceinline__ void subbands_store(
    float4* __restrict__ ob, size_t oidx,
    float4 T, float4 B, float tn, float bn)
{
    const float ts0 = T.x + T.y, ts1 = T.y + T.z, ts2 = T.z + T.w, ts3 = T.w + tn;
    const float td0 = T.x - T.y, td1 = T.y - T.z, td2 = T.z - T.w, td3 = T.w - tn;
    const float bs0 = B.x + B.y, bs1 = B.y + B.z, bs2 = B.z + B.w, bs3 = B.w + bn;
    const float bd0 = B.x - B.y, bd1 = B.y - B.z, bd2 = B.z - B.w, bd3 = B.w - bn;

    float4 v;
    v.x = 0.5f * (ts0 + bs0); v.y = 0.5f * (ts1 + bs1);
    v.z = 0.5f * (ts2 + bs2); v.w = 0.5f * (ts3 + bs3);
    __stcs(ob + oidx, v);                                   // LL

    v.x = 0.5f * (ts0 - bs0); v.y = 0.5f * (ts1 - bs1);
    v.z = 0.5f * (ts2 - bs2); v.w = 0.5f * (ts3 - bs3);
    __stcs(ob + PLANE4 + oidx, v);                          // LH

    v.x = 0.5f * (td0 + bd0); v.y = 0.5f * (td1 + bd1);
    v.z = 0.5f * (td2 + bd2); v.w = 0.5f * (td3 + bd3);
    __stcs(ob + 2 * PLANE4 + oidx, v);                      // HL

    v.x = 0.5f * (td0 - bd0); v.y = 0.5f * (td1 - bd1);
    v.z = 0.5f * (td2 - bd2); v.w = 0.5f * (td3 - bd3);
    __stcs(ob + 3 * PLANE4 + oidx, v);                      // HH
}

// block (32, 8): warp = 4 consecutive rows -> 32 rows/block. grid: (H/32, B*C)
__global__ __launch_bounds__(256)
void haar_dwt_kernel(const float* __restrict__ x, float* __restrict__ out)
{
    const int lane = threadIdx.x;                       // 0..31
    const int h0   = blockIdx.x * (8 * ROWS) + threadIdx.y * ROWS;
    const int bc   = blockIdx.y;

    const float4* xp4 = (const float4*)(x + (size_t)bc * DWT_H * DWT_W);
    float4* ob = (float4*)out + (size_t)(4 * bc) * PLANE4;

    // ---- preamble: load row h0 + its horizontal neighbors ----
    float4 cur1 = xp4[h0 * W4 + lane];        // cols [0,128)
    float4 cur2 = xp4[h0 * W4 + lane + 32];   // cols [128,256)
    float ncur1 = __shfl_down_sync(FULL, cur1.x, 1);
    float ncur2 = __shfl_down_sync(FULL, cur2.x, 1);
    {
        const float c2x0 = __shfl_sync(FULL, cur2.x, 0);
        if (lane == 31) { ncur1 = c2x0; ncur2 = 0.f; }
    }

#pragma unroll
    for (int r = 0; r < ROWS; r++) {
        const int hn = h0 + r + 1;
        float4 nxt1, nxt2;
        if (hn < DWT_H) {
            nxt1 = xp4[hn * W4 + lane];
            nxt2 = xp4[hn * W4 + lane + 32];
        } else {
            nxt1 = make_float4(0.f, 0.f, 0.f, 0.f);
            nxt2 = nxt1;
        }

        float nnxt1 = __shfl_down_sync(FULL, nxt1.x, 1);
        float nnxt2 = __shfl_down_sync(FULL, nxt2.x, 1);
        const float n2x0 = __shfl_sync(FULL, nxt2.x, 0);
        if (lane == 31) { nnxt1 = n2x0; nnxt2 = 0.f; }

        const size_t o = (size_t)(h0 + r) * W4 + lane;
        subbands_store(ob, o,      cur1, nxt1, ncur1, nnxt1);  // cols [0,128)
        subbands_store(ob, o + 32, cur2, nxt2, ncur2, nnxt2);  // cols [128,256)

        cur1 = nxt1;  cur2 = nxt2;
        ncur1 = nnxt1; ncur2 = nnxt2;
    }
}

extern "C" void kernel_launch(void* const* d_in, const int* in_sizes, int n_in,
                              void* d_out, int out_size)
{
    const float* x = (const float*)d_in[0];
    float* out = (float*)d_out;

    const int n_planes = in_sizes[0] / (DWT_H * DWT_W);   // B*C = 512

    dim3 block(32, 8, 1);
    dim3 grid(DWT_H / (8 * ROWS), n_planes, 1);
    haar_dwt_kernel<<<grid, block>>>(x, out);
}

// round 6
// speedup vs baseline: 1.0642x; 1.0642x over previous
#include <cuda_runtime.h>
#include <cuda_bf16.h>

// Haar DWT (pywt 'haar', torch-style flipped filters + cross-correlation):
//   a=x[h,w] b=x[h,w+1] c=x[h+1,w] d=x[h+1,w+1]  (zero pad right/bottom)
//   LL=.5(a+b+c+d)  LH=.5(a+b-c-d)  HL=.5(a-b+c-d)  HH=.5(a-b-c+d)
// out[b, 4c+k, h, w]  ->  plane index 4*(b*C+c)+k
//
// R6: warp = (row, half-row). 2x the warps of R3 (262K), shuffle-based
// horizontal neighbors, 2 front-batched LDG.128 + 4 STG.128 per thread,
// all 512B/warp. Only seam: one predicated lane-31 scalar __ldg (col 128)
// for group-0 warps.

#define DWT_W 256
#define DWT_H 256
#define W4    (DWT_W / 4)
#define PLANE4 ((size_t)DWT_H * W4)
#define FULL  0xffffffffu

// block (32, 8): 8 warps = 4 rows x 2 column groups. grid: (H/4, B*C)
__global__ __launch_bounds__(256)
void haar_dwt_kernel(const float* __restrict__ x, float* __restrict__ out)
{
    const int lane = threadIdx.x;                 // 0..31
    const int g    = threadIdx.y & 1;             // column group: 0 -> [0,128), 1 -> [128,256)
    const int h    = blockIdx.x * 4 + (threadIdx.y >> 1);   // output row
    const int bc   = blockIdx.y;

    const float*  xp  = x + (size_t)bc * DWT_H * DWT_W;
    const float4* xp4 = (const float4*)xp;

    const int  col4    = 32 * g + lane;           // float4 column 0..63
    const bool has_bot = (h < DWT_H - 1);

    // ---- front-batched loads: 2 independent 512B/warp LDG.128 ----
    float4 top = xp4[h * W4 + col4];
    float4 bot = has_bot ? xp4[(h + 1) * W4 + col4]
                         : make_float4(0.f, 0.f, 0.f, 0.f);

    // ---- horizontal neighbors via shuffle; seam handled by lane 31 ----
    float tn = __shfl_down_sync(FULL, top.x, 1);
    float bn = __shfl_down_sync(FULL, bot.x, 1);
    if (lane == 31) {
        if (g == 0) {           // neighbor is col 128 (first elem of group 1)
            tn = __ldg(&xp[h * DWT_W + 128]);
            bn = has_bot ? __ldg(&xp[(h + 1) * DWT_W + 128]) : 0.0f;
        } else {                // neighbor is col 256 -> zero pad
            tn = 0.0f;
            bn = 0.0f;
        }
    }

    // ---- horizontal sums/diffs shared by the 4 subbands ----
    const float ts0 = top.x + top.y, ts1 = top.y + top.z, ts2 = top.z + top.w, ts3 = top.w + tn;
    const float td0 = top.x - top.y, td1 = top.y - top.z, td2 = top.z - top.w, td3 = top.w - tn;
    const float bs0 = bot.x + bot.y, bs1 = bot.y + bot.z, bs2 = bot.z + bot.w, bs3 = bot.w + bn;
    const float bd0 = bot.x - bot.y, bd1 = bot.y - bot.z, bd2 = bot.z - bot.w, bd3 = bot.w - bn;

    float4* ob = (float4*)out + (size_t)(4 * bc) * PLANE4;
    const size_t oidx = (size_t)h * W4 + col4;

    float4 v;
    v.x = 0.5f * (ts0 + bs0); v.y = 0.5f * (ts1 + bs1);
    v.z = 0.5f * (ts2 + bs2); v.w = 0.5f * (ts3 + bs3);
    __stcs(ob + oidx, v);                                   // LL

    v.x = 0.5f * (ts0 - bs0); v.y = 0.5f * (ts1 - bs1);
    v.z = 0.5f * (ts2 - bs2); v.w = 0.5f * (ts3 - bs3);
    __stcs(ob + PLANE4 + oidx, v);                          // LH

    v.x = 0.5f * (td0 + bd0); v.y = 0.5f * (td1 + bd1);
    v.z = 0.5f * (td2 + bd2); v.w = 0.5f * (td3 + bd3);
    __stcs(ob + 2 * PLANE4 + oidx, v);                      // HL

    v.x = 0.5f * (td0 - bd0); v.y = 0.5f * (td1 - bd1);
    v.z = 0.5f * (td2 - bd2); v.w = 0.5f * (td3 - bd3);
    __stcs(ob + 3 * PLANE4 + oidx, v);                      // HH
}

extern "C" void kernel_launch(void* const* d_in, const int* in_sizes, int n_in,
                              void* d_out, int out_size)
{
    const float* x = (const float*)d_in[0];
    float* out = (float*)d_out;

    const int n_planes = in_sizes[0] / (DWT_H * DWT_W);   // B*C = 512

    dim3 block(32, 8, 1);
    dim3 grid(DWT_H / 4, n_planes, 1);
    haar_dwt_kernel<<<grid, block>>>(x, out);
}